// round 8
// baseline (speedup 1.0000x reference)
#include <cuda_runtime.h>

// BoxFilter fused separable 9x9 depthwise conv, fp32 NHWC.
// B=4, H=1080, W=1920, C=16 -> out [4, 1072, 1912, 16].
//
// Round-8: R7 was co-limited by DRAM (74%) and L1 (74%); the leaving-row L2
// reloads read the whole input a second time through L1. Changes:
//  * u64 granularity everywhere (2 channels/thread, 512 threads per 64-px
//    strip): 9-row rolling window is 18 regs -> fits 64-reg budget, so the
//    input is read from global EXACTLY once (no leaving-row reloads)
//  * __launch_bounds__(512,2), grid (35,2,4)=280 blocks, single wave,
//    32 warps/SM
//  * horizontal: 8 outputs/thread sliding 9-window sum (2.0 LDS.64/output),
//    taps loaded lazily (peak 9 live) to cap registers
//  * sb row stride SBU=568 u64 (=8 mod 16) keeps cross-row4 warp phases
//    bank-conflict-free

namespace {
constexpr int KS        = 9;
constexpr int Hh        = 1080;
constexpr int Ww        = 1920;
constexpr int Cc        = 16;
constexpr int OH        = 1072;       // H - 8
constexpr int OW        = 1912;       // W - 8
constexpr int EXT_PX    = 64;         // strip width incl. horizontal halo
constexpr int OUT_PX    = 56;         // output pixels per strip
constexpr int NTH       = 512;        // EXT_PX * 8 u64-lanes
constexpr int GRID_X    = 35;         // 35*56 >= 1912, last tile overlapped
constexpr int GRID_Y    = 2;
constexpr int ROWS_PB   = OH / GRID_Y;      // 536 output rows per block
constexpr int ITERS     = ROWS_PB / 4;      // 134 four-row iterations
constexpr int IN_ROWS   = ROWS_PB + 8;      // 544 input rows touched
constexpr int IN_ROW_U64  = Ww * Cc / 2;    // 15360 u64 per input row
constexpr int OUT_ROW_U64 = OW * Cc / 2;    // 15296 u64 per output row
constexpr int HTH       = 224;  // 4 rows * 7 groups * 8 u64-lanes
constexpr int SBU       = 568;  // padded u64 per row buffer (max idx 567)
}

typedef unsigned long long u64;

__device__ __forceinline__ void fma2(u64 &d, const u64 a, const u64 b) {
    asm("fma.rn.f32x2 %0, %1, %2, %0;" : "+l"(d) : "l"(a), "l"(b));
}
__device__ __forceinline__ void add2(u64 &d, const u64 a) {
    asm("add.rn.f32x2 %0, %0, %1;" : "+l"(d) : "l"(a));
}
__device__ __forceinline__ u64 mul2(const u64 a, const u64 b) {
    u64 r; asm("mul.rn.f32x2 %0, %1, %2;" : "=l"(r) : "l"(a), "l"(b));
    return r;
}
#define NEG1 0xBF800000BF800000ull
__device__ __forceinline__ void sub2(u64 &d, const u64 v) { fma2(d, NEG1, v); }

__device__ __forceinline__ u64 ldg1(const u64* p) {
    u64 v;
    asm volatile("ld.global.u64 %0, [%1];" : "=l"(v) : "l"(p));
    return v;
}
__device__ __forceinline__ void stcs1(u64* p, const u64 a) {
    asm volatile("st.global.cs.u64 [%0], %1;" :: "l"(p), "l"(a));
}

// padded u64 index within a row buffer: +8 u64 per 8-pixel group
__device__ __forceinline__ int sidx8(int p, int l) {
    return p * 8 + l + ((p >> 3) << 3);
}

// Horizontal: 8 outputs from 16 taps via sliding 9-window sum; lazy tap
// loads keep at most 9 taps live.
__device__ __forceinline__ void hphase8(const u64* __restrict__ s,
                                        u64* __restrict__ ob,
                                        const int hbase, const u64 scale)
{
    u64 t[9];
    #pragma unroll
    for (int j = 0; j < 9; ++j)
        t[j] = s[hbase + j * 8 + ((j >> 3) << 3)];
    u64 acc = t[0];
    #pragma unroll
    for (int j = 1; j < 9; ++j) add2(acc, t[j]);
    stcs1(ob, mul2(scale, acc));
    #pragma unroll
    for (int o = 1; o < 8; ++o) {
        const int j = o + 8;
        const u64 tn = s[hbase + j * 8 + ((j >> 3) << 3)];
        add2(acc, tn);
        sub2(acc, t[o - 1]);
        stcs1(ob + o * 8, mul2(scale, acc));
    }
}

__global__ void __launch_bounds__(NTH, 2)
box_kernel(const float* __restrict__ xg, const float* __restrict__ wyg,
           const float* __restrict__ wxg, float* __restrict__ og)
{
    __shared__ ulonglong2 wy_s[KS * 4];
    __shared__ ulonglong2 wx_s[KS * 4];
    __shared__ u64 sb[2][4][SBU];        // [buf][row-of-quad][padded u64]

    const int tid = threadIdx.x;
    const int ln  = tid & 7;             // u64 lane within pixel (2 channels)
    const int pl  = tid >> 3;            // pixel within strip, 0..63

    const int bx = blockIdx.x, by = blockIdx.y, bz = blockIdx.z;
    const int px0 = min(bx * OUT_PX, OW - OUT_PX);   // overlapped last tile
    const int r0  = by * ROWS_PB;

    const ulonglong2* wyv = reinterpret_cast<const ulonglong2*>(wyg);
    const ulonglong2* wxv = reinterpret_cast<const ulonglong2*>(wxg);
    if (tid < KS * 4)                    wy_s[tid]      = wyv[tid];
    else if (tid >= 64 && tid < 64 + 36) wx_s[tid - 64] = wxv[tid - 64];
    __syncthreads();

    // Block-wide bitwise uniformity vote (each thread checks one quad).
    int myuni = 1;
    {
        const int q = tid & 3;
        const ulonglong2 y0 = wy_s[q], x0 = wx_s[q];
        #pragma unroll
        for (int k = 1; k < KS; ++k) {
            const ulonglong2 yk = wy_s[k * 4 + q], xk = wx_s[k * 4 + q];
            myuni &= (yk.x == y0.x) & (yk.y == y0.y)
                   & (xk.x == x0.x) & (xk.y == x0.y);
        }
    }
    const int uniform = __syncthreads_and(myuni);

    const u64* ib = reinterpret_cast<const u64*>(xg)
        + (size_t)(bz * Hh + r0) * IN_ROW_U64 + (px0 + pl) * 8 + ln;
    const int sst = sidx8(pl, ln);
    const u64* wyu = reinterpret_cast<const u64*>(wy_s);
    const u64* wxu = reinterpret_cast<const u64*>(wx_s);

    if (uniform) {
        // ---------- fast path: running sums, 4 rows/iter, 1x input ----------
        const bool hact  = (tid < HTH);
        const int  hq    = tid & 7;
        const int  hrest = tid >> 3;          // 0..27 when active
        const int  row4  = hrest / 7;
        const int  gx    = hrest - row4 * 7;  // 8-px output group
        const int  hbase = 72 * gx + hq;

        const u64 scale = mul2(wyu[hq], wxu[hq]);

        u64* ob = reinterpret_cast<u64*>(og)
            + (size_t)(bz * OH + r0 + row4) * OUT_ROW_U64
            + (size_t)(px0 + gx * 8) * 8 + hq;

        // Prologue: window = rows 0..8, S = their sum.
        u64 win[8], cur, S;
        win[0] = ldg1(ib); S = win[0];
        #pragma unroll
        for (int k = 1; k < 8; ++k) {
            win[k] = ldg1(ib + k * IN_ROW_U64);
            add2(S, win[k]);
        }
        cur = ldg1(ib + 8 * IN_ROW_U64);
        add2(S, cur);

        // Iteration 0 (peeled): rows 0..3.
        {
            const u64 Ln0 = ldg1(ib +  9 * IN_ROW_U64);
            const u64 Ln1 = ldg1(ib + 10 * IN_ROW_U64);
            const u64 Ln2 = ldg1(ib + 11 * IN_ROW_U64);
            const u64 Ln3 = ldg1(ib + 12 * IN_ROW_U64);

            sb[0][0][sst] = S;
            add2(S, Ln0); sub2(S, win[0]); sb[0][1][sst] = S;
            add2(S, Ln1); sub2(S, win[1]); sb[0][2][sst] = S;
            add2(S, Ln2); sub2(S, win[2]); sb[0][3][sst] = S;
            add2(S, Ln3); sub2(S, win[3]);

            win[0] = win[4]; win[1] = win[5]; win[2] = win[6]; win[3] = win[7];
            win[4] = cur; win[5] = Ln0; win[6] = Ln1; win[7] = Ln2;
            cur = Ln3;
            __syncthreads();
        }

        for (int i = 1; i < ITERS; ++i) {
            const int r = 4 * i;
            // 1) the only global reads: 4 new rows (DRAM-critical)
            const u64 Ln0 = ldg1(ib + (r +  9) * IN_ROW_U64);
            const u64 Ln1 = ldg1(ib + (r + 10) * IN_ROW_U64);
            const u64 Ln2 = ldg1(ib + (r + 11) * IN_ROW_U64);
            const u64 Ln3 = ldg1(ib + min(r + 12, IN_ROWS - 1) * IN_ROW_U64);

            // 2) horizontal for iter i-1 (covers load latency)
            if (hact) {
                hphase8(sb[(i - 1) & 1][row4], ob, hbase, scale);
                ob += 4 * OUT_ROW_U64;
            }

            // 3) vertical advance: rows r..r+3 into sb[i&1]
            const int buf = i & 1;
            sb[buf][0][sst] = S;
            add2(S, Ln0); sub2(S, win[0]); sb[buf][1][sst] = S;
            add2(S, Ln1); sub2(S, win[1]); sb[buf][2][sst] = S;
            add2(S, Ln2); sub2(S, win[2]); sb[buf][3][sst] = S;
            add2(S, Ln3); sub2(S, win[3]);

            win[0] = win[4]; win[1] = win[5]; win[2] = win[6]; win[3] = win[7];
            win[4] = cur; win[5] = Ln0; win[6] = Ln1; win[7] = Ln2;
            cur = Ln3;

            __syncthreads();
        }

        // Epilogue: horizontal for the last iteration.
        if (hact)
            hphase8(sb[(ITERS - 1) & 1][row4], ob, hbase, scale);
    } else {
        // ---------- fallback: full 9-tap FMA (any weights), u64 lanes ----------
        const bool emit = (pl < OUT_PX);
        u64* op = reinterpret_cast<u64*>(og)
            + (size_t)(bz * OH + r0) * OUT_ROW_U64 + (px0 + pl) * 8 + ln;

        u64 win[8], cur, nxt;
        #pragma unroll
        for (int k = 0; k < 8; ++k) win[k] = ldg1(ib + k * IN_ROW_U64);
        cur = ldg1(ib + 8 * IN_ROW_U64);
        nxt = ldg1(ib + 9 * IN_ROW_U64);

        for (int i = 0; i < ROWS_PB / 2; ++i) {
            u64 p0 = cur, p1 = cur;
            if (2 * i + 10 < IN_ROWS) p0 = ldg1(ib + (2 * i + 10) * IN_ROW_U64);
            if (2 * i + 11 < IN_ROWS) p1 = ldg1(ib + (2 * i + 11) * IN_ROW_U64);

            u64 a0 = 0, a1 = 0;
            #pragma unroll
            for (int k = 0; k < KS; ++k) {
                const u64 w   = wyu[k * 8 + ln];
                const u64 r0v = (k < 8) ? win[k] : cur;
                const u64 r1v = (k < 7) ? win[k + 1] : ((k == 7) ? cur : nxt);
                fma2(a0, w, r0v);
                fma2(a1, w, r1v);
            }
            const int buf = i & 1;
            sb[buf][0][sst] = a0;
            sb[buf][1][sst] = a1;

            #pragma unroll
            for (int k = 0; k < 6; ++k) win[k] = win[k + 2];
            win[6] = cur; win[7] = nxt;
            cur = p0; nxt = p1;

            __syncthreads();

            if (emit) {
                u64 o0 = 0, o1 = 0;
                #pragma unroll
                for (int j = 0; j < KS; ++j) {
                    const u64 w  = wxu[j * 8 + ln];
                    const u64 t0 = sb[buf][0][sidx8(pl + j, ln)];
                    const u64 t1 = sb[buf][1][sidx8(pl + j, ln)];
                    fma2(o0, w, t0);
                    fma2(o1, w, t1);
                }
                op[0]           = o0;
                op[OUT_ROW_U64] = o1;
            }
            op += 2 * OUT_ROW_U64;
            __syncthreads();
        }
    }
}

extern "C" void kernel_launch(void* const* d_in, const int* in_sizes, int n_in,
                              void* d_out, int out_size)
{
    const float* x  = (const float*)d_in[0];
    const float* wy = (const float*)d_in[1];
    const float* wx = (const float*)d_in[2];
    float* out = (float*)d_out;

    dim3 grid(GRID_X, GRID_Y, 4);
    dim3 block(NTH);
    box_kernel<<<grid, block>>>(x, wy, wx, out);
}